// round 9
// baseline (speedup 1.0000x reference)
#include <cuda_runtime.h>
#include <math.h>
#include <stdint.h>

// Problem constants
#define B_  32
#define DM  512
#define S_  64
#define L_  4096
#define KSPLIT3 4    // split-K for step 3 (K=4096 -> 4 x 1024)

// ---------------------------------------------------------------------------
// Scratch (device globals - no allocation allowed)
// ---------------------------------------------------------------------------
__device__ float g_braw [(size_t)B_ * 3 * S_ * L_];        // [B,192,4096] pre-conv
__device__ float g_cm   [(size_t)B_ * S_ * L_];            // [B,64,4096]  conv'd C [s][l]
__device__ float g_ab   [(size_t)B_ * S_ * L_];            // [B,64,4096]  softmax(dt)*Bm [s][l]
__device__ float g_hpart[(size_t)KSPLIT3 * DM * B_ * S_];  // [4,512,2048] split-K partials
__device__ float g_hcb  [(size_t)DM * B_ * S_];            // [512,2048]   h in [c][b*64+s]
__device__ float g_hz   [(size_t)2 * DM * B_ * S_];        // [1024,2048]
__device__ float g_hg   [(size_t)DM * B_ * S_];            // [512,2048]

// ===========================================================================
// TF32 warp-MMA GEMM (mma.sync m16n8k8 — baseline PTX, works on compute_103)
// Register-prefetch pipelined mainloop (next chunk's LDG overlaps MMA).
// ===========================================================================

static __device__ __forceinline__ uint32_t f2tf(float x) {
    uint32_t u;
    asm("cvt.rna.tf32.f32 %0, %1;" : "=r"(u) : "f"(x));
    return u;
}

static __device__ __forceinline__ void mma8(float* c, const uint32_t* a,
                                            uint32_t b0, uint32_t b1) {
    asm volatile(
        "mma.sync.aligned.m16n8k8.row.col.f32.tf32.tf32.f32 "
        "{%0,%1,%2,%3}, {%4,%5,%6,%7}, {%8,%9}, {%0,%1,%2,%3};"
        : "+f"(c[0]), "+f"(c[1]), "+f"(c[2]), "+f"(c[3])
        : "r"(a[0]), "r"(a[1]), "r"(a[2]), "r"(a[3]), "r"(b0), "r"(b1));
}

// smem tile layout: 32 words per row, word (row, k) stored at
//   row*32 + (k ^ ((row & 7) << 2))
// -> fragment LDS conflict-free; K-contig float4 staging conflict-free.
#define SWZ(row, k) (((row) << 5) + ((k) ^ (((row) & 7) << 2)))

// ---------------------------------------------------------------------------
// gemm_mma<NT, BT, KSP, EPI>:
//   C[M, N](tile 128 x NT) = A[M,K] . op(B)  in tf32, fp32 accum, +bias[row].
//   A: [Mtot, K] row-major (K contig), lda; rows >= Mtot are zero-padded.
//   BT=0: B is [N, K] row-major (K contig), ldb   (requires NT == 64)
//   BT=1: B is [K, N] row-major (N contig), ldb — transposed during staging
//         (requires NT == 128)
//   KSP: split-K segments; blockIdx.z = bz * KSP + kseg.
//   EPI=0: C row-major (ldc).  EPI=1: col n scattered to (n>>6)*DM*S_+row*S_+(n&63).
// ---------------------------------------------------------------------------
template <int NT, bool BT, int KSP, int EPI>
__global__ void __launch_bounds__(256) gemm_mma(
    const float* __restrict__ A, long long sA, int lda,
    const float* __restrict__ B, long long sB, int ldb,
    float* __restrict__ C, long long sC, int ldc, long long segStride,
    const float* __restrict__ bias, int Mtot, int K)
{
    constexpr int MT = (NT == 128) ? 2 : 1;   // mma m-tiles per warp
    constexpr int NB = BT ? 4 : 2;            // B prefetch float4 count

    __shared__ uint32_t As[128 * 32];
    __shared__ uint32_t Bs[NT * 32];

    const int zz = blockIdx.z;
    const int bz = zz / KSP, kseg = zz % KSP;
    A += (size_t)bz * sA;
    B += (size_t)bz * sB;
    C += (size_t)bz * sC + (size_t)kseg * segStride;

    const int m0 = blockIdx.y * 128;
    const int n0 = blockIdx.x * NT;
    const int tid  = threadIdx.x;
    const int w    = tid >> 5;
    const int lane = tid & 31;
    const int gid  = lane >> 2;   // 0..7
    const int tig  = lane & 3;    // 0..3

    const int mBase = (NT == 128) ? ((w >> 1) * 32) : (w * 16);
    const int nBase = (NT == 128) ? ((w & 1) * 64) : 0;

    float acc[MT][8][4] = {};

    // A staging: thread -> (row ar, 16-float half ah)
    const int ar = tid >> 1;
    const int ah = (tid & 1) << 4;
    const bool avalid = (m0 + ar) < Mtot;

    // B staging indices
    const int bk_t  = tid >> 3;          // BT: 0..31 (k)
    const int bn0_t = (tid & 7) << 4;    // BT: 0..112 (n)
    const int br_t  = tid >> 2;          // !BT: 0..63 (n)
    const int bq_t  = (tid & 3) << 3;    // !BT: 0,8,16,24 (k)

    const int Kseg = K / KSP;
    const int kbeg = kseg * Kseg;
    const int nch  = Kseg >> 5;

    float4 va[4];     // A prefetch regs
    float4 vb[NB];    // B prefetch regs

    // ---- load chunk k0 into registers ----
    auto load_chunk = [&](int k0) {
        const float* ap = A + (size_t)(m0 + ar) * lda + k0 + ah;
#pragma unroll
        for (int j = 0; j < 4; j++)
            va[j] = avalid ? *(const float4*)(ap + j * 4)
                           : make_float4(0.f, 0.f, 0.f, 0.f);
        if (BT) {
            const float* bp = B + (size_t)(k0 + bk_t) * ldb + n0 + bn0_t;
#pragma unroll
            for (int j = 0; j < NB; j++)
                vb[j] = *(const float4*)(bp + j * 4);
        } else {
            const float* bp = B + (size_t)br_t * ldb + k0 + bq_t;
#pragma unroll
            for (int j = 0; j < NB; j++)
                vb[j] = *(const float4*)(bp + j * 4);
        }
    };

    // ---- store register chunk to smem (tf32-rounded, swizzled) ----
    auto store_chunk = [&]() {
#pragma unroll
        for (int j = 0; j < 4; j++) {
            uint4 u;
            u.x = f2tf(va[j].x); u.y = f2tf(va[j].y);
            u.z = f2tf(va[j].z); u.w = f2tf(va[j].w);
            *(uint4*)&As[SWZ(ar, ah + j * 4)] = u;
        }
        if (BT) {
#pragma unroll
            for (int j = 0; j < NB; j++) {
                const int nl = bn0_t + j * 4;
                Bs[SWZ(nl + 0, bk_t)] = f2tf(vb[j].x);
                Bs[SWZ(nl + 1, bk_t)] = f2tf(vb[j].y);
                Bs[SWZ(nl + 2, bk_t)] = f2tf(vb[j].z);
                Bs[SWZ(nl + 3, bk_t)] = f2tf(vb[j].w);
            }
        } else {
#pragma unroll
            for (int j = 0; j < NB; j++) {
                uint4 u;
                u.x = f2tf(vb[j].x); u.y = f2tf(vb[j].y);
                u.z = f2tf(vb[j].z); u.w = f2tf(vb[j].w);
                *(uint4*)&Bs[SWZ(br_t, bq_t + j * 4)] = u;
            }
        }
    };

    // prologue: stage chunk 0
    load_chunk(kbeg);
    store_chunk();
    __syncthreads();

    for (int c = 0; c < nch; c++) {
        const bool more = (c + 1 < nch);
        if (more) load_chunk(kbeg + ((c + 1) << 5));   // LDG overlaps MMAs below

        // ---- compute: 4 k-steps of 8 ----
#pragma unroll
        for (int ks = 0; ks < 4; ks++) {
            const int kk = ks << 3;
            uint32_t af[MT][4];
#pragma unroll
            for (int mt = 0; mt < MT; mt++) {
                const int r = mBase + mt * 16 + gid;
                af[mt][0] = As[SWZ(r,     kk + tig)];
                af[mt][1] = As[SWZ(r + 8, kk + tig)];
                af[mt][2] = As[SWZ(r,     kk + tig + 4)];
                af[mt][3] = As[SWZ(r + 8, kk + tig + 4)];
            }
#pragma unroll
            for (int nt = 0; nt < 8; nt++) {
                const int cc = nBase + nt * 8 + gid;
                const uint32_t b0 = Bs[SWZ(cc, kk + tig)];
                const uint32_t b1 = Bs[SWZ(cc, kk + tig + 4)];
#pragma unroll
                for (int mt = 0; mt < MT; mt++)
                    mma8(acc[mt][nt], af[mt], b0, b1);
            }
        }
        __syncthreads();
        if (more) {
            store_chunk();
            __syncthreads();
        }
    }

    // ---- epilogue ----
#pragma unroll
    for (int mt = 0; mt < MT; mt++) {
#pragma unroll
        for (int nt = 0; nt < 8; nt++) {
            const int row = m0 + mBase + mt * 16 + gid;
            const int col = n0 + nBase + nt * 8 + tig * 2;
            const float* a = acc[mt][nt];
#pragma unroll
            for (int h = 0; h < 2; h++) {
                const int r = row + h * 8;
                if (r < Mtot) {
                    const float bi = bias ? bias[r] : 0.0f;
                    float2 o;
                    o.x = a[h * 2 + 0] + bi;
                    o.y = a[h * 2 + 1] + bi;
                    if (EPI == 0) {
                        *(float2*)(C + (size_t)r * ldc + col) = o;
                    } else {
                        float* cp = C + (size_t)(col >> 6) * (DM * S_)
                                      + (size_t)r * S_ + (col & 63);
                        *(float2*)cp = o;
                    }
                }
            }
        }
    }
}

// ---------------------------------------------------------------------------
// Reduce split-K partials: hcb = sum of KSPLIT3 slabs of [512,2048]
// ---------------------------------------------------------------------------
__global__ void __launch_bounds__(256) reduce_splitk(
    const float4* __restrict__ in, float4* __restrict__ out)
{
    const int n4 = (DM * B_ * S_) / 4;  // 262144
    const int i = blockIdx.x * 256 + threadIdx.x;
    if (i >= n4) return;
    float4 s = in[i];
#pragma unroll
    for (int k = 1; k < KSPLIT3; k++) {
        float4 v = in[i + (size_t)k * n4];
        s.x += v.x; s.y += v.y; s.z += v.z; s.w += v.w;
    }
    out[i] = s;
}

// ---------------------------------------------------------------------------
// Fused depthwise 3x3 conv + softmax + AB. One block per (s, b).
// A[s] is constant along the softmax axis -> cancels; Bm never hits memory.
// ---------------------------------------------------------------------------
__global__ void __launch_bounds__(256) conv_softmax_ab(
    const float* __restrict__ braw,
    const float* __restrict__ w_dw, const float* __restrict__ b_dw,
    float* __restrict__ cm, float* __restrict__ ab)
{
    __shared__ float sin[4096];
    __shared__ float red[256];

    const int s  = blockIdx.x;
    const int b  = blockIdx.y;
    const int tid = threadIdx.x;
    const size_t base = (size_t)b * (3 * S_ * L_);

    float r[16], p[16], w[9];

    {   // dt channel -> softmax probs
        const int ch = 128 + s;
        const float* ip = braw + base + (size_t)ch * 4096;
        for (int k = 0; k < 16; k++) sin[tid + k * 256] = ip[tid + k * 256];
#pragma unroll
        for (int j = 0; j < 9; j++) w[j] = w_dw[ch * 9 + j];
        const float bv = b_dw[ch];
        __syncthreads();

#pragma unroll
        for (int k = 0; k < 16; k++) {
            const int idx = k * 256 + tid;
            const int i = idx >> 6, j = idx & 63;
            float acc = bv;
#pragma unroll
            for (int di = 0; di < 3; di++) {
                const int ii = i + di - 1;
                if (ii < 0 || ii > 63) continue;
#pragma unroll
                for (int dj = 0; dj < 3; dj++) {
                    const int jj = j + dj - 1;
                    if (jj < 0 || jj > 63) continue;
                    acc += w[di * 3 + dj] * sin[(ii << 6) + jj];
                }
            }
            r[k] = acc;
        }
        float mx = r[0];
#pragma unroll
        for (int k = 1; k < 16; k++) mx = fmaxf(mx, r[k]);
        red[tid] = mx; __syncthreads();
        for (int off = 128; off > 0; off >>= 1) {
            if (tid < off) red[tid] = fmaxf(red[tid], red[tid + off]);
            __syncthreads();
        }
        mx = red[0]; __syncthreads();
        float sum = 0.0f;
#pragma unroll
        for (int k = 0; k < 16; k++) { p[k] = expf(r[k] - mx); sum += p[k]; }
        red[tid] = sum; __syncthreads();
        for (int off = 128; off > 0; off >>= 1) {
            if (tid < off) red[tid] += red[tid + off];
            __syncthreads();
        }
        const float inv = 1.0f / red[0];
#pragma unroll
        for (int k = 0; k < 16; k++) p[k] *= inv;
        __syncthreads();
    }

    {   // Bm channel -> AB = p * conv(Bm)
        const int ch = s;
        const float* ip = braw + base + (size_t)ch * 4096;
        for (int k = 0; k < 16; k++) sin[tid + k * 256] = ip[tid + k * 256];
#pragma unroll
        for (int j = 0; j < 9; j++) w[j] = w_dw[ch * 9 + j];
        const float bv = b_dw[ch];
        __syncthreads();

        float* op = ab + (size_t)b * (S_ * L_) + (size_t)s * 4096;
#pragma unroll
        for (int k = 0; k < 16; k++) {
            const int idx = k * 256 + tid;
            const int i = idx >> 6, j = idx & 63;
            float acc = bv;
#pragma unroll
            for (int di = 0; di < 3; di++) {
                const int ii = i + di - 1;
                if (ii < 0 || ii > 63) continue;
#pragma unroll
                for (int dj = 0; dj < 3; dj++) {
                    const int jj = j + dj - 1;
                    if (jj < 0 || jj > 63) continue;
                    acc += w[di * 3 + dj] * sin[(ii << 6) + jj];
                }
            }
            op[idx] = p[k] * acc;
        }
        __syncthreads();
    }

    {   // Cm channel -> cm
        const int ch = 64 + s;
        const float* ip = braw + base + (size_t)ch * 4096;
        for (int k = 0; k < 16; k++) sin[tid + k * 256] = ip[tid + k * 256];
#pragma unroll
        for (int j = 0; j < 9; j++) w[j] = w_dw[ch * 9 + j];
        const float bv = b_dw[ch];
        __syncthreads();

        float* op = cm + (size_t)b * (S_ * L_) + (size_t)s * 4096;
#pragma unroll
        for (int k = 0; k < 16; k++) {
            const int idx = k * 256 + tid;
            const int i = idx >> 6, j = idx & 63;
            float acc = bv;
#pragma unroll
            for (int di = 0; di < 3; di++) {
                const int ii = i + di - 1;
                if (ii < 0 || ii > 63) continue;
#pragma unroll
                for (int dj = 0; dj < 3; dj++) {
                    const int jj = j + dj - 1;
                    if (jj < 0 || jj > 63) continue;
                    acc += w[di * 3 + dj] * sin[(ii << 6) + jj];
                }
            }
            op[idx] = acc;
        }
    }
}

// Gating: hg = h1 * (z*sigmoid(z) + Dskip), layout [o][b*64+s]
__global__ void __launch_bounds__(256) gate_kernel(
    const float* __restrict__ hz, float* __restrict__ hg,
    const float* __restrict__ Dskip)
{
    const int total = DM * B_ * S_;
    const int i = blockIdx.x * 256 + threadIdx.x;
    if (i >= total) return;
    const float h1 = hz[i];
    const float z  = hz[i + total];
    const float sig = 1.0f / (1.0f + expf(-z));
    hg[i] = h1 * (z * sig + Dskip[0]);
}

// ===========================================================================
// Host launch
// ===========================================================================
extern "C" void kernel_launch(void* const* d_in, const int* in_sizes, int n_in,
                              void* d_out, int out_size)
{
    (void)in_sizes; (void)n_in; (void)out_size;

    const float* x      = (const float*)d_in[0];   // [32,512,4096]
    const float* w_bcdt = (const float*)d_in[1];   // [192,512]
    const float* b_bcdt = (const float*)d_in[2];   // [192]
    const float* w_dw   = (const float*)d_in[3];   // [192,1,3,3]
    const float* b_dw   = (const float*)d_in[4];   // [192]
    const float* w_hz   = (const float*)d_in[5];   // [1024,512]
    const float* b_hz   = (const float*)d_in[6];   // [1024]
    const float* w_out  = (const float*)d_in[7];   // [512,512]
    const float* b_out  = (const float*)d_in[8];   // [512]
    const float* Dskip  = (const float*)d_in[10];  // [1] (A at [9] cancels in softmax)

    float* out = (float*)d_out;
    float* y   = out;                               // [32,512,4096]
    float* ho  = out + (size_t)B_ * DM * L_;        // [32,512,64]

    float *braw, *cm, *ab, *hpart, *hcb, *hz, *hg;
    cudaGetSymbolAddress((void**)&braw,  g_braw);
    cudaGetSymbolAddress((void**)&cm,    g_cm);
    cudaGetSymbolAddress((void**)&ab,    g_ab);
    cudaGetSymbolAddress((void**)&hpart, g_hpart);
    cudaGetSymbolAddress((void**)&hcb,   g_hcb);
    cudaGetSymbolAddress((void**)&hz,    g_hz);
    cudaGetSymbolAddress((void**)&hg,    g_hg);

    const dim3 blk(256);

    // 1) braw[b] = w_bcdt @ x[b] + b_bcdt   (M=192, N=4096, K=512)  B = x (N contig)
    gemm_mma<128, true, 1, 0><<<dim3(L_ / 128, 2, B_), blk>>>(
        w_bcdt, 0, DM,
        x, (long long)DM * L_, L_,
        braw, (long long)3 * S_ * L_, L_, 0,
        b_bcdt, 192, DM);

    // 2) fused dwconv + softmax + AB / Cm
    conv_softmax_ab<<<dim3(S_, B_), blk>>>(braw, w_dw, b_dw, cm, ab);

    // 3) hpart[kseg] = x[b] @ AB[b]^T  (M=512, N=64, K=4096, split-K=4)
    //    output into [c][b*64+s] layout: C = hpart + kseg*1048576 + bz*64
    gemm_mma<64, false, KSPLIT3, 0><<<dim3(1, DM / 128, B_ * KSPLIT3), blk>>>(
        x, (long long)DM * L_, L_,
        ab, (long long)S_ * L_, L_,
        hpart, 64, B_ * S_, (long long)DM * B_ * S_,
        nullptr, DM, L_);

    // 4) reduce partials -> hcb [512][2048]
    reduce_splitk<<<(DM * B_ * S_ / 4 + 255) / 256, blk>>>(
        (const float4*)hpart, (float4*)hcb);

    // 5) hz = w_hz @ hcb + b_hz   (M=1024, N=2048, K=512)  B = hcb (N contig)
    gemm_mma<128, true, 1, 0><<<dim3(B_ * S_ / 128, 8, 1), blk>>>(
        w_hz, 0, DM,
        hcb, 0, B_ * S_,
        hz, 0, B_ * S_, 0,
        b_hz, 2 * DM, DM);

    // 6) gating
    gate_kernel<<<(DM * B_ * S_ + 255) / 256, blk>>>(hz, hg, Dskip);

    // 7) ho = w_out @ hg + b_out, scattered into d_out [b][512][64]
    gemm_mma<128, true, 1, 1><<<dim3(B_ * S_ / 128, 4, 1), blk>>>(
        w_out, 0, DM,
        hg, 0, B_ * S_,
        ho, 0, 0, 0,
        b_out, DM, DM);

    // 8) y[b] = ho[b] @ Cm[b]   (M=512, N=4096, K=64)  B = cm (N contig)
    gemm_mma<128, true, 1, 0><<<dim3(L_ / 128, 4, B_), blk>>>(
        ho, (long long)DM * S_, S_,
        cm, (long long)S_ * L_, L_,
        y, (long long)DM * L_, L_, 0,
        nullptr, DM, S_);
}

// round 10
// speedup vs baseline: 1.1852x; 1.1852x over previous
#include <cuda_runtime.h>
#include <cuda_fp16.h>
#include <math.h>
#include <stdint.h>

// Problem constants
#define B_  32
#define DM  512
#define S_  64
#define L_  4096
#define KSPLIT3 4    // split-K for step 3 (K=4096 -> 4 x 1024)
#define AB_SCALE 1024.0f   // keeps ab out of fp16 subnormal range

// ---------------------------------------------------------------------------
// Scratch (device globals - no allocation allowed)
// ---------------------------------------------------------------------------
__device__ float g_braw [(size_t)B_ * 3 * S_ * L_];        // [B,192,4096] pre-conv
__device__ float g_cm   [(size_t)B_ * S_ * L_];            // [B,64,4096]  conv'd C [s][l]
__device__ float g_ab   [(size_t)B_ * S_ * L_];            // [B,64,4096]  AB_SCALE*softmax(dt)*Bm
__device__ float g_hpart[(size_t)KSPLIT3 * DM * B_ * S_];  // [4,512,2048] split-K partials
__device__ float g_hcb  [(size_t)DM * B_ * S_];            // [512,2048]   h in [c][b*64+s]
__device__ float g_hz   [(size_t)2 * DM * B_ * S_];        // [1024,2048]
__device__ float g_hg   [(size_t)DM * B_ * S_];            // [512,2048]

// ===========================================================================
// FP16 warp-MMA GEMM (mma.sync m16n8k16, fp32 accum — baseline PTX)
// fp16 mantissa (10 bits) == tf32 mantissa, HMMA rate 2x tf32.
// R8 bulk-synchronous loop (no register prefetch — occupancy hides latency).
// ===========================================================================

static __device__ __forceinline__ uint32_t h2u(__half2 h) {
    return *(uint32_t*)&h;
}

static __device__ __forceinline__ void mma16(float* c, const uint32_t* a,
                                             uint32_t b0, uint32_t b1) {
    asm volatile(
        "mma.sync.aligned.m16n8k16.row.col.f32.f16.f16.f32 "
        "{%0,%1,%2,%3}, {%4,%5,%6,%7}, {%8,%9}, {%0,%1,%2,%3};"
        : "+f"(c[0]), "+f"(c[1]), "+f"(c[2]), "+f"(c[3])
        : "r"(a[0]), "r"(a[1]), "r"(a[2]), "r"(a[3]), "r"(b0), "r"(b1));
}

// smem tile: 16 half2-words per row; word (row, kp) holds halves k=2kp, 2kp+1.
//   addr = row*16 + (kp ^ (((row>>1)&3)<<2))
// Fragment LDS (8 rows x kp {tig, tig+4}): same-parity rows get disjoint
// 4-bank groups -> conflict-free. K-contig uint4 staging stays 4-aligned.
#define SWZH(row, kp) (((row) << 4) + ((kp) ^ ((((row) >> 1) & 3) << 2)))

// ---------------------------------------------------------------------------
// gemm_mma<NT, BT, KSP, EPI>:
//   C[M, N](tile 128 x NT) = A[M,K] . op(B)  in fp16, fp32 accum, +bias[row].
//   A: [Mtot, K] row-major (K contig), lda; rows >= Mtot are zero-padded.
//   BT=0: B is [N, K] row-major (K contig), ldb   (requires NT == 64)
//   BT=1: B is [K, N] row-major (N contig), ldb — transposed during staging
//         (requires NT == 128)
//   KSP: split-K segments; blockIdx.z = bz * KSP + kseg.
//   EPI=0: C row-major (ldc).  EPI=1: col n scattered to (n>>6)*DM*S_+row*S_+(n&63).
// ---------------------------------------------------------------------------
template <int NT, bool BT, int KSP, int EPI>
__global__ void __launch_bounds__(256) gemm_mma(
    const float* __restrict__ A, long long sA, int lda,
    const float* __restrict__ B, long long sB, int ldb,
    float* __restrict__ C, long long sC, int ldc, long long segStride,
    const float* __restrict__ bias, int Mtot, int K)
{
    constexpr int MT = (NT == 128) ? 2 : 1;   // mma m-tiles per warp

    __shared__ uint32_t As[128 * 16];
    __shared__ uint32_t Bs[NT * 16];

    const int zz = blockIdx.z;
    const int bz = zz / KSP, kseg = zz % KSP;
    A += (size_t)bz * sA;
    B += (size_t)bz * sB;
    C += (size_t)bz * sC + (size_t)kseg * segStride;

    const int m0 = blockIdx.y * 128;
    const int n0 = blockIdx.x * NT;
    const int tid  = threadIdx.x;
    const int w    = tid >> 5;
    const int lane = tid & 31;
    const int gid  = lane >> 2;   // 0..7
    const int tig  = lane & 3;    // 0..3

    const int mBase = (NT == 128) ? ((w >> 1) * 32) : (w * 16);
    const int nBase = (NT == 128) ? ((w & 1) * 64) : 0;

    float acc[MT][8][4] = {};

    // A staging: thread -> (row ar, kp-block kb of 8)
    const int ar = tid >> 1;
    const int kb = (tid & 1) << 3;          // kp base: 0 or 8
    const bool avalid = (m0 + ar) < Mtot;

    // B staging indices
    const int bk_t  = tid >> 3;             // BT: 0..31 (k)
    const int bn0_t = (tid & 7) << 4;       // BT: 0..112 (n)
    const int br_t  = tid >> 2;             // !BT: 0..63 (n)
    const int bkb_t = (tid & 3) << 2;       // !BT: kp base 0,4,8,12

    const int Kseg = K / KSP;
    const int kbeg = kseg * Kseg;
    const int nch  = Kseg >> 5;

    for (int c = 0; c < nch; c++) {
        const int k0 = kbeg + (c << 5);

        // ---- stage A [128 rows x 32 k] as half2 ----
        {
            const float* ap = A + (size_t)(m0 + ar) * lda + k0 + kb * 2;
            float4 v0, v1, v2, v3;
            if (avalid) {
                v0 = *(const float4*)(ap + 0);
                v1 = *(const float4*)(ap + 4);
                v2 = *(const float4*)(ap + 8);
                v3 = *(const float4*)(ap + 12);
            } else {
                v0 = v1 = v2 = v3 = make_float4(0.f, 0.f, 0.f, 0.f);
            }
            uint4 w0, w1;
            w0.x = h2u(__floats2half2_rn(v0.x, v0.y));
            w0.y = h2u(__floats2half2_rn(v0.z, v0.w));
            w0.z = h2u(__floats2half2_rn(v1.x, v1.y));
            w0.w = h2u(__floats2half2_rn(v1.z, v1.w));
            w1.x = h2u(__floats2half2_rn(v2.x, v2.y));
            w1.y = h2u(__floats2half2_rn(v2.z, v2.w));
            w1.z = h2u(__floats2half2_rn(v3.x, v3.y));
            w1.w = h2u(__floats2half2_rn(v3.z, v3.w));
            *(uint4*)&As[SWZH(ar, kb)]     = w0;
            *(uint4*)&As[SWZH(ar, kb + 4)] = w1;
        }

        // ---- stage B [NT rows(n) x 32 k] ----
        if (BT) {
            // B[k][n] (n contig): transpose during staging. NT == 128.
            const float* bp = B + (size_t)(k0 + bk_t) * ldb + n0 + bn0_t;
            const int kp = bk_t >> 1, hsel = bk_t & 1;
            __half* bh = (__half*)Bs;
#pragma unroll
            for (int j = 0; j < 4; j++) {
                float4 v = *(const float4*)(bp + j * 4);
                const int nl = bn0_t + j * 4;
                bh[SWZH(nl + 0, kp) * 2 + hsel] = __float2half_rn(v.x);
                bh[SWZH(nl + 1, kp) * 2 + hsel] = __float2half_rn(v.y);
                bh[SWZH(nl + 2, kp) * 2 + hsel] = __float2half_rn(v.z);
                bh[SWZH(nl + 3, kp) * 2 + hsel] = __float2half_rn(v.w);
            }
        } else {
            // B[n][k] (K contig). NT == 64.
            const float* bp = B + (size_t)br_t * ldb + k0 + bkb_t * 2;
            float4 v0 = *(const float4*)(bp + 0);
            float4 v1 = *(const float4*)(bp + 4);
            uint4 u;
            u.x = h2u(__floats2half2_rn(v0.x, v0.y));
            u.y = h2u(__floats2half2_rn(v0.z, v0.w));
            u.z = h2u(__floats2half2_rn(v1.x, v1.y));
            u.w = h2u(__floats2half2_rn(v1.z, v1.w));
            *(uint4*)&Bs[SWZH(br_t, bkb_t)] = u;
        }

        __syncthreads();

        // ---- compute: 2 k-steps of 16 ----
#pragma unroll
        for (int ks = 0; ks < 2; ks++) {
            const int kpb = ks << 3;
            uint32_t af[MT][4];
#pragma unroll
            for (int mt = 0; mt < MT; mt++) {
                const int r = mBase + mt * 16 + gid;
                af[mt][0] = As[SWZH(r,     kpb + tig)];
                af[mt][1] = As[SWZH(r + 8, kpb + tig)];
                af[mt][2] = As[SWZH(r,     kpb + tig + 4)];
                af[mt][3] = As[SWZH(r + 8, kpb + tig + 4)];
            }
#pragma unroll
            for (int nt = 0; nt < 8; nt++) {
                const int cc = nBase + nt * 8 + gid;
                const uint32_t b0 = Bs[SWZH(cc, kpb + tig)];
                const uint32_t b1 = Bs[SWZH(cc, kpb + tig + 4)];
#pragma unroll
                for (int mt = 0; mt < MT; mt++)
                    mma16(acc[mt][nt], af[mt], b0, b1);
            }
        }
        __syncthreads();
    }

    // ---- epilogue ----
#pragma unroll
    for (int mt = 0; mt < MT; mt++) {
#pragma unroll
        for (int nt = 0; nt < 8; nt++) {
            const int row = m0 + mBase + mt * 16 + gid;
            const int col = n0 + nBase + nt * 8 + tig * 2;
            const float* a = acc[mt][nt];
#pragma unroll
            for (int h = 0; h < 2; h++) {
                const int r = row + h * 8;
                if (r < Mtot) {
                    const float bi = bias ? bias[r] : 0.0f;
                    float2 o;
                    o.x = a[h * 2 + 0] + bi;
                    o.y = a[h * 2 + 1] + bi;
                    if (EPI == 0) {
                        *(float2*)(C + (size_t)r * ldc + col) = o;
                    } else {
                        float* cp = C + (size_t)(col >> 6) * (DM * S_)
                                      + (size_t)r * S_ + (col & 63);
                        *(float2*)cp = o;
                    }
                }
            }
        }
    }
}

// ---------------------------------------------------------------------------
// Reduce split-K partials: hcb = (1/AB_SCALE) * sum of KSPLIT3 slabs
// ---------------------------------------------------------------------------
__global__ void __launch_bounds__(256) reduce_splitk(
    const float4* __restrict__ in, float4* __restrict__ out)
{
    const int n4 = (DM * B_ * S_) / 4;  // 262144
    const int i = blockIdx.x * 256 + threadIdx.x;
    if (i >= n4) return;
    float4 s = in[i];
#pragma unroll
    for (int k = 1; k < KSPLIT3; k++) {
        float4 v = in[i + (size_t)k * n4];
        s.x += v.x; s.y += v.y; s.z += v.z; s.w += v.w;
    }
    const float inv = 1.0f / AB_SCALE;
    s.x *= inv; s.y *= inv; s.z *= inv; s.w *= inv;
    out[i] = s;
}

// ---------------------------------------------------------------------------
// Fused depthwise 3x3 conv + softmax + AB. One block per (s, b).
// A[s] is constant along the softmax axis -> cancels; Bm never hits memory.
// ab output pre-scaled by AB_SCALE (fp16 subnormal avoidance).
// ---------------------------------------------------------------------------
__global__ void __launch_bounds__(256) conv_softmax_ab(
    const float* __restrict__ braw,
    const float* __restrict__ w_dw, const float* __restrict__ b_dw,
    float* __restrict__ cm, float* __restrict__ ab)
{
    __shared__ float sin[4096];
    __shared__ float red[256];

    const int s  = blockIdx.x;
    const int b  = blockIdx.y;
    const int tid = threadIdx.x;
    const size_t base = (size_t)b * (3 * S_ * L_);

    float r[16], p[16], w[9];

    {   // dt channel -> softmax probs
        const int ch = 128 + s;
        const float* ip = braw + base + (size_t)ch * 4096;
        for (int k = 0; k < 16; k++) sin[tid + k * 256] = ip[tid + k * 256];
#pragma unroll
        for (int j = 0; j < 9; j++) w[j] = w_dw[ch * 9 + j];
        const float bv = b_dw[ch];
        __syncthreads();

#pragma unroll
        for (int k = 0; k < 16; k++) {
            const int idx = k * 256 + tid;
            const int i = idx >> 6, j = idx & 63;
            float acc = bv;
#pragma unroll
            for (int di = 0; di < 3; di++) {
                const int ii = i + di - 1;
                if (ii < 0 || ii > 63) continue;
#pragma unroll
                for (int dj = 0; dj < 3; dj++) {
                    const int jj = j + dj - 1;
                    if (jj < 0 || jj > 63) continue;
                    acc += w[di * 3 + dj] * sin[(ii << 6) + jj];
                }
            }
            r[k] = acc;
        }
        float mx = r[0];
#pragma unroll
        for (int k = 1; k < 16; k++) mx = fmaxf(mx, r[k]);
        red[tid] = mx; __syncthreads();
        for (int off = 128; off > 0; off >>= 1) {
            if (tid < off) red[tid] = fmaxf(red[tid], red[tid + off]);
            __syncthreads();
        }
        mx = red[0]; __syncthreads();
        float sum = 0.0f;
#pragma unroll
        for (int k = 0; k < 16; k++) { p[k] = expf(r[k] - mx); sum += p[k]; }
        red[tid] = sum; __syncthreads();
        for (int off = 128; off > 0; off >>= 1) {
            if (tid < off) red[tid] += red[tid + off];
            __syncthreads();
        }
        const float inv = AB_SCALE / red[0];
#pragma unroll
        for (int k = 0; k < 16; k++) p[k] *= inv;
        __syncthreads();
    }

    {   // Bm channel -> AB = p * conv(Bm)   (p carries AB_SCALE)
        const int ch = s;
        const float* ip = braw + base + (size_t)ch * 4096;
        for (int k = 0; k < 16; k++) sin[tid + k * 256] = ip[tid + k * 256];
#pragma unroll
        for (int j = 0; j < 9; j++) w[j] = w_dw[ch * 9 + j];
        const float bv = b_dw[ch];
        __syncthreads();

        float* op = ab + (size_t)b * (S_ * L_) + (size_t)s * 4096;
#pragma unroll
        for (int k = 0; k < 16; k++) {
            const int idx = k * 256 + tid;
            const int i = idx >> 6, j = idx & 63;
            float acc = bv;
#pragma unroll
            for (int di = 0; di < 3; di++) {
                const int ii = i + di - 1;
                if (ii < 0 || ii > 63) continue;
#pragma unroll
                for (int dj = 0; dj < 3; dj++) {
                    const int jj = j + dj - 1;
                    if (jj < 0 || jj > 63) continue;
                    acc += w[di * 3 + dj] * sin[(ii << 6) + jj];
                }
            }
            op[idx] = p[k] * acc;
        }
        __syncthreads();
    }

    {   // Cm channel -> cm
        const int ch = 64 + s;
        const float* ip = braw + base + (size_t)ch * 4096;
        for (int k = 0; k < 16; k++) sin[tid + k * 256] = ip[tid + k * 256];
#pragma unroll
        for (int j = 0; j < 9; j++) w[j] = w_dw[ch * 9 + j];
        const float bv = b_dw[ch];
        __syncthreads();

        float* op = cm + (size_t)b * (S_ * L_) + (size_t)s * 4096;
#pragma unroll
        for (int k = 0; k < 16; k++) {
            const int idx = k * 256 + tid;
            const int i = idx >> 6, j = idx & 63;
            float acc = bv;
#pragma unroll
            for (int di = 0; di < 3; di++) {
                const int ii = i + di - 1;
                if (ii < 0 || ii > 63) continue;
#pragma unroll
                for (int dj = 0; dj < 3; dj++) {
                    const int jj = j + dj - 1;
                    if (jj < 0 || jj > 63) continue;
                    acc += w[di * 3 + dj] * sin[(ii << 6) + jj];
                }
            }
            op[idx] = acc;
        }
    }
}

// Gating: hg = h1 * (z*sigmoid(z) + Dskip), layout [o][b*64+s]
__global__ void __launch_bounds__(256) gate_kernel(
    const float* __restrict__ hz, float* __restrict__ hg,
    const float* __restrict__ Dskip)
{
    const int total = DM * B_ * S_;
    const int i = blockIdx.x * 256 + threadIdx.x;
    if (i >= total) return;
    const float h1 = hz[i];
    const float z  = hz[i + total];
    const float sig = 1.0f / (1.0f + expf(-z));
    hg[i] = h1 * (z * sig + Dskip[0]);
}

// ===========================================================================
// Host launch
// ===========================================================================
extern "C" void kernel_launch(void* const* d_in, const int* in_sizes, int n_in,
                              void* d_out, int out_size)
{
    (void)in_sizes; (void)n_in; (void)out_size;

    const float* x      = (const float*)d_in[0];   // [32,512,4096]
    const float* w_bcdt = (const float*)d_in[1];   // [192,512]
    const float* b_bcdt = (const float*)d_in[2];   // [192]
    const float* w_dw   = (const float*)d_in[3];   // [192,1,3,3]
    const float* b_dw   = (const float*)d_in[4];   // [192]
    const float* w_hz   = (const float*)d_in[5];   // [1024,512]
    const float* b_hz   = (const float*)d_in[6];   // [1024]
    const float* w_out  = (const float*)d_in[7];   // [512,512]
    const float* b_out  = (const float*)d_in[8];   // [512]
    const float* Dskip  = (const float*)d_in[10];  // [1] (A at [9] cancels in softmax)

    float* out = (float*)d_out;
    float* y   = out;                               // [32,512,4096]
    float* ho  = out + (size_t)B_ * DM * L_;        // [32,512,64]

    float *braw, *cm, *ab, *hpart, *hcb, *hz, *hg;
    cudaGetSymbolAddress((void**)&braw,  g_braw);
    cudaGetSymbolAddress((void**)&cm,    g_cm);
    cudaGetSymbolAddress((void**)&ab,    g_ab);
    cudaGetSymbolAddress((void**)&hpart, g_hpart);
    cudaGetSymbolAddress((void**)&hcb,   g_hcb);
    cudaGetSymbolAddress((void**)&hz,    g_hz);
    cudaGetSymbolAddress((void**)&hg,    g_hg);

    const dim3 blk(256);

    // 1) braw[b] = w_bcdt @ x[b] + b_bcdt   (M=192, N=4096, K=512)  B = x (N contig)
    gemm_mma<128, true, 1, 0><<<dim3(L_ / 128, 2, B_), blk>>>(
        w_bcdt, 0, DM,
        x, (long long)DM * L_, L_,
        braw, (long long)3 * S_ * L_, L_, 0,
        b_bcdt, 192, DM);

    // 2) fused dwconv + softmax + AB / Cm  (ab pre-scaled by AB_SCALE)
    conv_softmax_ab<<<dim3(S_, B_), blk>>>(braw, w_dw, b_dw, cm, ab);

    // 3) hpart[kseg] = x[b] @ AB[b]^T  (M=512, N=64, K=4096, split-K=4)
    gemm_mma<64, false, KSPLIT3, 0><<<dim3(1, DM / 128, B_ * KSPLIT3), blk>>>(
        x, (long long)DM * L_, L_,
        ab, (long long)S_ * L_, L_,
        hpart, 64, B_ * S_, (long long)DM * B_ * S_,
        nullptr, DM, L_);

    // 4) reduce partials (and /AB_SCALE) -> hcb [512][2048]
    reduce_splitk<<<(DM * B_ * S_ / 4 + 255) / 256, blk>>>(
        (const float4*)hpart, (float4*)hcb);

    // 5) hz = w_hz @ hcb + b_hz   (M=1024, N=2048, K=512)  B = hcb (N contig)
    gemm_mma<128, true, 1, 0><<<dim3(B_ * S_ / 128, 8, 1), blk>>>(
        w_hz, 0, DM,
        hcb, 0, B_ * S_,
        hz, 0, B_ * S_, 0,
        b_hz, 2 * DM, DM);

    // 6) gating
    gate_kernel<<<(DM * B_ * S_ + 255) / 256, blk>>>(hz, hg, Dskip);

    // 7) ho = w_out @ hg + b_out, scattered into d_out [b][512][64]
    gemm_mma<128, true, 1, 1><<<dim3(B_ * S_ / 128, 4, 1), blk>>>(
        w_out, 0, DM,
        hg, 0, B_ * S_,
        ho, 0, 0, 0,
        b_out, DM, DM);

    // 8) y[b] = ho[b] @ Cm[b]   (M=512, N=4096, K=64)  B = cm (N contig)
    gemm_mma<128, true, 1, 0><<<dim3(L_ / 128, 4, B_), blk>>>(
        ho, (long long)DM * S_, S_,
        cm, (long long)S_ * L_, L_,
        y, (long long)DM * L_, L_, 0,
        nullptr, DM, S_);
}

// round 13
// speedup vs baseline: 1.7173x; 1.4490x over previous
#include <cuda_runtime.h>
#include <cuda_fp16.h>
#include <math.h>
#include <stdint.h>

// Problem constants
#define B_  32
#define DM  512
#define S_  64
#define L_  4096
#define KSPLIT3 4          // split-K for step 3 (K=4096 -> 4 x 1024)
#define AB_SCALE 1024.0f   // keeps ab out of fp16 subnormal range

// ---------------------------------------------------------------------------
// Scratch (device globals - no allocation allowed)
// ---------------------------------------------------------------------------
__device__ float  g_braw [(size_t)B_ * 3 * S_ * L_];        // [B,192,4096] pre-conv
__device__ float  g_cm   [(size_t)B_ * S_ * L_];            // [B,64,4096] conv'd C [s][l] fp32
__device__ float  g_hpart[(size_t)KSPLIT3 * DM * B_ * S_];  // [4,512,2048] split-K partials
__device__ float  g_hcb  [(size_t)DM * B_ * S_];            // [512,2048]
__device__ float  g_hz   [(size_t)2 * DM * B_ * S_];        // [1024,2048]
__device__ float  g_hg   [(size_t)DM * B_ * S_];            // [512,2048]
__device__ __half g_x16  [(size_t)B_ * DM * L_];            // x  [b][c][l] fp16
__device__ __half g_x16t [(size_t)B_ * L_ * DM];            // x^T [b][l][c] fp16
__device__ __half g_ab16 [(size_t)B_ * S_ * L_];            // AB_SCALE*softmax*Bm [b][s][l]
__device__ __half g_cm16t[(size_t)B_ * L_ * S_];            // cm^T [b][l][s] fp16
__device__ __half g_w16  [(size_t)256 * DM];                // w_bcdt zero-padded to 256 rows
__device__ __half g_ho16 [(size_t)B_ * DM * S_];            // ho fp16 [b][c][s]

// smem tile: 16 half2-words per row; word (row, kp) holds halves k=2kp, 2kp+1.
//   addr = row*16 + (kp ^ (((row>>1)&3)<<2))
// xor touches only bits>=2 of kp -> 16B groups (kp%4==0) stay contiguous,
// so cp.async 16B chunks land correctly. Fragment LDS conflict-free.
#define SWZH(row, kp) (((row) << 4) + ((kp) ^ ((((row) >> 1) & 3) << 2)))

static __device__ __forceinline__ uint32_t h2u(__half2 h) {
    return *(uint32_t*)&h;
}

static __device__ __forceinline__ void mma16(float* c, const uint32_t* a,
                                             uint32_t b0, uint32_t b1) {
    asm volatile(
        "mma.sync.aligned.m16n8k16.row.col.f32.f16.f16.f32 "
        "{%0,%1,%2,%3}, {%4,%5,%6,%7}, {%8,%9}, {%0,%1,%2,%3};"
        : "+f"(c[0]), "+f"(c[1]), "+f"(c[2]), "+f"(c[3])
        : "r"(a[0]), "r"(a[1]), "r"(a[2]), "r"(a[3]), "r"(b0), "r"(b1));
}

// ===========================================================================
// gemm_h16<NT, KSP>: fp16-operand GEMM, cp.async double-buffered.
//   C[M,N](tile 128 x NT) = A[M,K] . B[N,K]^T, fp32 accum, +bias[row].
//   A: [*,K] fp16 K-contig lda (rows >= 128*grid must be readable: pre-padded).
//   B: [N,K] fp16 K-contig ldb.
//   KSP split-K: blockIdx.z = bz*KSP + kseg; C += bz*sC + kseg*segStride.
//   C fp32 row-major ldc; epilogue guards row < Mtot.
// ===========================================================================
template <int NT, int KSP>
__global__ void __launch_bounds__(256) gemm_h16(
    const __half* __restrict__ A, long long sA, int lda,
    const __half* __restrict__ B, long long sB, int ldb,
    float* __restrict__ C, long long sC, int ldc, long long segStride,
    const float* __restrict__ bias, int Mtot, int K)
{
    constexpr int MT = (NT == 128) ? 2 : 1;

    __shared__ __align__(16) uint32_t As[2][128 * 16];
    __shared__ __align__(16) uint32_t Bs[2][NT * 16];

    const int zz = blockIdx.z;
    const int bz = zz / KSP, kseg = zz % KSP;
    A += (size_t)bz * sA;
    B += (size_t)bz * sB;
    C += (size_t)bz * sC + (size_t)kseg * segStride;

    const int m0 = blockIdx.y * 128;
    const int n0 = blockIdx.x * NT;
    const int tid  = threadIdx.x;
    const int w    = tid >> 5;
    const int lane = tid & 31;
    const int gid  = lane >> 2;
    const int tig  = lane & 3;

    const int mBase = (NT == 128) ? ((w >> 1) * 32) : (w * 16);
    const int nBase = (NT == 128) ? ((w & 1) * 64) : 0;

    float acc[MT][8][4] = {};

    const int Kseg = K / KSP;
    const int kbeg = kseg * Kseg;
    const int nch  = Kseg >> 5;

    // stage chunk k0 into buffer buf via cp.async (16B per op)
    const int s_row = tid >> 2;            // 0..63 base row unit
    const int s_kpb = (tid & 3) << 2;      // kp base 0,4,8,12

    for (int c = 0; c < nch; c++) {
        if (c == 0) {
            // prologue stage chunk 0
            const int k0 = kbeg;
#pragma unroll
            for (int j = 0; j < 2; j++) {
                const int row = s_row + j * 64;
                const __half* src = A + (size_t)(m0 + row) * lda + k0 + (s_kpb << 1);
                uint32_t dst = (uint32_t)__cvta_generic_to_shared(&As[0][SWZH(row, s_kpb)]);
                asm volatile("cp.async.ca.shared.global [%0], [%1], 16;\n" :: "r"(dst), "l"(src));
            }
#pragma unroll
            for (int j = 0; j < NT / 64; j++) {
                const int row = s_row + j * 64;
                const __half* src = B + (size_t)(n0 + row) * ldb + k0 + (s_kpb << 1);
                uint32_t dst = (uint32_t)__cvta_generic_to_shared(&Bs[0][SWZH(row, s_kpb)]);
                asm volatile("cp.async.ca.shared.global [%0], [%1], 16;\n" :: "r"(dst), "l"(src));
            }
            asm volatile("cp.async.commit_group;\n");
        }
        if (c + 1 < nch) {
            // prefetch chunk c+1 into alternate buffer
            const int k0 = kbeg + ((c + 1) << 5);
            const int buf = (c + 1) & 1;
#pragma unroll
            for (int j = 0; j < 2; j++) {
                const int row = s_row + j * 64;
                const __half* src = A + (size_t)(m0 + row) * lda + k0 + (s_kpb << 1);
                uint32_t dst = (uint32_t)__cvta_generic_to_shared(&As[buf][SWZH(row, s_kpb)]);
                asm volatile("cp.async.ca.shared.global [%0], [%1], 16;\n" :: "r"(dst), "l"(src));
            }
#pragma unroll
            for (int j = 0; j < NT / 64; j++) {
                const int row = s_row + j * 64;
                const __half* src = B + (size_t)(n0 + row) * ldb + k0 + (s_kpb << 1);
                uint32_t dst = (uint32_t)__cvta_generic_to_shared(&Bs[buf][SWZH(row, s_kpb)]);
                asm volatile("cp.async.ca.shared.global [%0], [%1], 16;\n" :: "r"(dst), "l"(src));
            }
            asm volatile("cp.async.commit_group;\n");
            asm volatile("cp.async.wait_group 1;\n");
        } else {
            asm volatile("cp.async.wait_group 0;\n");
        }
        __syncthreads();

        const uint32_t* Ab = As[c & 1];
        const uint32_t* Bb = Bs[c & 1];

#pragma unroll
        for (int ks = 0; ks < 2; ks++) {
            const int kpb = ks << 3;
            uint32_t af[MT][4];
#pragma unroll
            for (int mt = 0; mt < MT; mt++) {
                const int r = mBase + mt * 16 + gid;
                af[mt][0] = Ab[SWZH(r,     kpb + tig)];
                af[mt][1] = Ab[SWZH(r + 8, kpb + tig)];
                af[mt][2] = Ab[SWZH(r,     kpb + tig + 4)];
                af[mt][3] = Ab[SWZH(r + 8, kpb + tig + 4)];
            }
#pragma unroll
            for (int nt = 0; nt < 8; nt++) {
                const int cc = nBase + nt * 8 + gid;
                const uint32_t b0 = Bb[SWZH(cc, kpb + tig)];
                const uint32_t b1 = Bb[SWZH(cc, kpb + tig + 4)];
#pragma unroll
                for (int mt = 0; mt < MT; mt++)
                    mma16(acc[mt][nt], af[mt], b0, b1);
            }
        }
        __syncthreads();
    }

    // ---- epilogue ----
#pragma unroll
    for (int mt = 0; mt < MT; mt++) {
#pragma unroll
        for (int nt = 0; nt < 8; nt++) {
            const int row = m0 + mBase + mt * 16 + gid;
            const int col = n0 + nBase + nt * 8 + tig * 2;
            const float* a = acc[mt][nt];
#pragma unroll
            for (int h = 0; h < 2; h++) {
                const int r = row + h * 8;
                if (r < Mtot) {
                    const float bi = bias ? bias[r] : 0.0f;
                    float2 o;
                    o.x = a[h * 2 + 0] + bi;
                    o.y = a[h * 2 + 1] + bi;
                    *(float2*)(C + (size_t)r * ldc + col) = o;
                }
            }
        }
    }
}

// ===========================================================================
// gemm_mma<NT, BT, KSP, EPI>: fp32-input fp16-compute kernel (steps 5/7).
// EPI=1 additionally writes an fp16 copy to ho16 (same scatter addresses).
// ===========================================================================
template <int NT, bool BT, int KSP, int EPI>
__global__ void __launch_bounds__(256) gemm_mma(
    const float* __restrict__ A, long long sA, int lda,
    const float* __restrict__ B, long long sB, int ldb,
    float* __restrict__ C, long long sC, int ldc, long long segStride,
    const float* __restrict__ bias, int Mtot, int K, __half* __restrict__ ho16)
{
    constexpr int MT = (NT == 128) ? 2 : 1;

    __shared__ uint32_t As[128 * 16];
    __shared__ uint32_t Bs[NT * 16];

    const int zz = blockIdx.z;
    const int bz = zz / KSP, kseg = zz % KSP;
    A += (size_t)bz * sA;
    B += (size_t)bz * sB;
    C += (size_t)bz * sC + (size_t)kseg * segStride;

    const int m0 = blockIdx.y * 128;
    const int n0 = blockIdx.x * NT;
    const int tid  = threadIdx.x;
    const int w    = tid >> 5;
    const int lane = tid & 31;
    const int gid  = lane >> 2;
    const int tig  = lane & 3;

    const int mBase = (NT == 128) ? ((w >> 1) * 32) : (w * 16);
    const int nBase = (NT == 128) ? ((w & 1) * 64) : 0;

    float acc[MT][8][4] = {};

    const int ar = tid >> 1;
    const int kb = (tid & 1) << 3;
    const bool avalid = (m0 + ar) < Mtot;

    const int bk_t  = tid >> 3;
    const int bn0_t = (tid & 7) << 4;
    const int br_t  = tid >> 2;
    const int bkb_t = (tid & 3) << 2;

    const int Kseg = K / KSP;
    const int kbeg = kseg * Kseg;
    const int nch  = Kseg >> 5;

    for (int c = 0; c < nch; c++) {
        const int k0 = kbeg + (c << 5);

        {
            const float* ap = A + (size_t)(m0 + ar) * lda + k0 + kb * 2;
            float4 v0, v1, v2, v3;
            if (avalid) {
                v0 = *(const float4*)(ap + 0);
                v1 = *(const float4*)(ap + 4);
                v2 = *(const float4*)(ap + 8);
                v3 = *(const float4*)(ap + 12);
            } else {
                v0 = v1 = v2 = v3 = make_float4(0.f, 0.f, 0.f, 0.f);
            }
            uint4 w0, w1;
            w0.x = h2u(__floats2half2_rn(v0.x, v0.y));
            w0.y = h2u(__floats2half2_rn(v0.z, v0.w));
            w0.z = h2u(__floats2half2_rn(v1.x, v1.y));
            w0.w = h2u(__floats2half2_rn(v1.z, v1.w));
            w1.x = h2u(__floats2half2_rn(v2.x, v2.y));
            w1.y = h2u(__floats2half2_rn(v2.z, v2.w));
            w1.z = h2u(__floats2half2_rn(v3.x, v3.y));
            w1.w = h2u(__floats2half2_rn(v3.z, v3.w));
            *(uint4*)&As[SWZH(ar, kb)]     = w0;
            *(uint4*)&As[SWZH(ar, kb + 4)] = w1;
        }

        if (BT) {
            const float* bp = B + (size_t)(k0 + bk_t) * ldb + n0 + bn0_t;
            const int kp = bk_t >> 1, hsel = bk_t & 1;
            __half* bh = (__half*)Bs;
#pragma unroll
            for (int j = 0; j < 4; j++) {
                float4 v = *(const float4*)(bp + j * 4);
                const int nl = bn0_t + j * 4;
                bh[SWZH(nl + 0, kp) * 2 + hsel] = __float2half_rn(v.x);
                bh[SWZH(nl + 1, kp) * 2 + hsel] = __float2half_rn(v.y);
                bh[SWZH(nl + 2, kp) * 2 + hsel] = __float2half_rn(v.z);
                bh[SWZH(nl + 3, kp) * 2 + hsel] = __float2half_rn(v.w);
            }
        } else {
            const float* bp = B + (size_t)br_t * ldb + k0 + bkb_t * 2;
            float4 v0 = *(const float4*)(bp + 0);
            float4 v1 = *(const float4*)(bp + 4);
            uint4 u;
            u.x = h2u(__floats2half2_rn(v0.x, v0.y));
            u.y = h2u(__floats2half2_rn(v0.z, v0.w));
            u.z = h2u(__floats2half2_rn(v1.x, v1.y));
            u.w = h2u(__floats2half2_rn(v1.z, v1.w));
            *(uint4*)&Bs[SWZH(br_t, bkb_t)] = u;
        }

        __syncthreads();

#pragma unroll
        for (int ks = 0; ks < 2; ks++) {
            const int kpb = ks << 3;
            uint32_t af[MT][4];
#pragma unroll
            for (int mt = 0; mt < MT; mt++) {
                const int r = mBase + mt * 16 + gid;
                af[mt][0] = As[SWZH(r,     kpb + tig)];
                af[mt][1] = As[SWZH(r + 8, kpb + tig)];
                af[mt][2] = As[SWZH(r,     kpb + tig + 4)];
                af[mt][3] = As[SWZH(r + 8, kpb + tig + 4)];
            }
#pragma unroll
            for (int nt = 0; nt < 8; nt++) {
                const int cc = nBase + nt * 8 + gid;
                const uint32_t b0 = Bs[SWZH(cc, kpb + tig)];
                const uint32_t b1 = Bs[SWZH(cc, kpb + tig + 4)];
#pragma unroll
                for (int mt = 0; mt < MT; mt++)
                    mma16(acc[mt][nt], af[mt], b0, b1);
            }
        }
        __syncthreads();
    }

#pragma unroll
    for (int mt = 0; mt < MT; mt++) {
#pragma unroll
        for (int nt = 0; nt < 8; nt++) {
            const int row = m0 + mBase + mt * 16 + gid;
            const int col = n0 + nBase + nt * 8 + tig * 2;
            const float* a = acc[mt][nt];
#pragma unroll
            for (int h = 0; h < 2; h++) {
                const int r = row + h * 8;
                if (r < Mtot) {
                    const float bi = bias ? bias[r] : 0.0f;
                    float2 o;
                    o.x = a[h * 2 + 0] + bi;
                    o.y = a[h * 2 + 1] + bi;
                    if (EPI == 0) {
                        *(float2*)(C + (size_t)r * ldc + col) = o;
                    } else {
                        const size_t off = (size_t)(col >> 6) * (DM * S_)
                                         + (size_t)r * S_ + (col & 63);
                        *(float2*)(C + off) = o;
                        *(__half2*)(ho16 + off) = __floats2half2_rn(o.x, o.y);
                    }
                }
            }
        }
    }
}

// ---------------------------------------------------------------------------
// cvt_xt: fp32 [b][R][C] -> optional straight fp16 copy + transposed fp16
// [b][C][R]. 64x64 tiles via smem. Requires R%64==0, C%64==0.
// ---------------------------------------------------------------------------
__global__ void __launch_bounds__(256) cvt_xt(
    const float* __restrict__ in, __half* __restrict__ outS,
    __half* __restrict__ outT, int R, int C)
{
    __shared__ __align__(16) __half t[64][72];
    const int tid = threadIdx.x;
    const int b  = blockIdx.z;
    const int r0 = blockIdx.y * 64, c0 = blockIdx.x * 64;
    const float* ip = in + (size_t)b * R * C;
    const int q = (tid & 15) * 4;

#pragma unroll
    for (int it = 0; it < 4; it++) {
        const int r = (tid >> 4) + it * 16;
        float4 v = *(const float4*)(ip + (size_t)(r0 + r) * C + c0 + q);
        __half2 p0 = __floats2half2_rn(v.x, v.y);
        __half2 p1 = __floats2half2_rn(v.z, v.w);
        if (outS) {
            __half* os = outS + (size_t)b * R * C + (size_t)(r0 + r) * C + c0 + q;
            *(__half2*)(os)     = p0;
            *(__half2*)(os + 2) = p1;
        }
        t[q + 0][r] = __low2half(p0);
        t[q + 1][r] = __high2half(p0);
        t[q + 2][r] = __low2half(p1);
        t[q + 3][r] = __high2half(p1);
    }
    __syncthreads();

    __half* ot = outT + (size_t)b * R * C;   // [C][R]
#pragma unroll
    for (int it = 0; it < 2; it++) {
        const int idx = tid + it * 256;      // 0..511
        const int l = idx >> 3, cc = (idx & 7) * 8;
        *(uint4*)(ot + (size_t)(c0 + l) * R + r0 + cc) = *(const uint4*)&t[l][cc];
    }
}

// w_bcdt [192][512] fp32 -> [256][512] fp16 zero-padded
__global__ void __launch_bounds__(256) cvt_w(
    const float* __restrict__ w, __half* __restrict__ w16)
{
    const int i = blockIdx.x * 256 + threadIdx.x;
    if (i >= 256 * DM) return;
    const int r = i >> 9;
    w16[i] = (r < 192) ? __float2half_rn(w[i]) : __half(0.f);
}

// ---------------------------------------------------------------------------
// Reduce split-K partials: hcb = (1/AB_SCALE) * sum of KSPLIT3 slabs
// ---------------------------------------------------------------------------
__global__ void __launch_bounds__(256) reduce_splitk(
    const float4* __restrict__ in, float4* __restrict__ out)
{
    const int n4 = (DM * B_ * S_) / 4;
    const int i = blockIdx.x * 256 + threadIdx.x;
    if (i >= n4) return;
    float4 s = in[i];
#pragma unroll
    for (int k = 1; k < KSPLIT3; k++) {
        float4 v = in[i + (size_t)k * n4];
        s.x += v.x; s.y += v.y; s.z += v.z; s.w += v.w;
    }
    const float inv = 1.0f / AB_SCALE;
    s.x *= inv; s.y *= inv; s.z *= inv; s.w *= inv;
    out[i] = s;
}

// ---------------------------------------------------------------------------
// Fused depthwise 3x3 conv + softmax + AB. One block per (s, b).
// ab16 output fp16, pre-scaled by AB_SCALE. cm output fp32 (transposed later).
// ---------------------------------------------------------------------------
__global__ void __launch_bounds__(256) conv_softmax_ab(
    const float* __restrict__ braw,
    const float* __restrict__ w_dw, const float* __restrict__ b_dw,
    float* __restrict__ cm, __half* __restrict__ ab16)
{
    __shared__ float sin[4096];
    __shared__ float red[256];

    const int s  = blockIdx.x;
    const int b  = blockIdx.y;
    const int tid = threadIdx.x;
    const size_t base = (size_t)b * (3 * S_ * L_);

    float r[16], p[16], w[9];

    {   // dt channel -> softmax probs
        const int ch = 128 + s;
        const float* ip = braw + base + (size_t)ch * 4096;
        for (int k = 0; k < 16; k++) sin[tid + k * 256] = ip[tid + k * 256];
#pragma unroll
        for (int j = 0; j < 9; j++) w[j] = w_dw[ch * 9 + j];
        const float bv = b_dw[ch];
        __syncthreads();

#pragma unroll
        for (int k = 0; k < 16; k++) {
            const int idx = k * 256 + tid;
            const int i = idx >> 6, j = idx & 63;
            float acc = bv;
#pragma unroll
            for (int di = 0; di < 3; di++) {
                const int ii = i + di - 1;
                if (ii < 0 || ii > 63) continue;
#pragma unroll
                for (int dj = 0; dj < 3; dj++) {
                    const int jj = j + dj - 1;
                    if (jj < 0 || jj > 63) continue;
                    acc += w[di * 3 + dj] * sin[(ii << 6) + jj];
                }
            }
            r[k] = acc;
        }
        float mx = r[0];
#pragma unroll
        for (int k = 1; k < 16; k++) mx = fmaxf(mx, r[k]);
        red[tid] = mx; __syncthreads();
        for (int off = 128; off > 0; off >>= 1) {
            if (tid < off) red[tid] = fmaxf(red[tid], red[tid + off]);
            __syncthreads();
        }
        mx = red[0]; __syncthreads();
        float sum = 0.0f;
#pragma unroll
        for (int k = 0; k < 16; k++) { p[k] = expf(r[k] - mx); sum += p[k]; }
        red[tid] = sum; __syncthreads();
        for (int off = 128; off > 0; off >>= 1) {
            if (tid < off) red[tid] += red[tid + off];
            __syncthreads();
        }
        const float inv = AB_SCALE / red[0];
#pragma unroll
        for (int k = 0; k < 16; k++) p[k] *= inv;
        __syncthreads();
    }

    {   // Bm channel -> ab16 = p * conv(Bm)   (p carries AB_SCALE)
        const int ch = s;
        const float* ip = braw + base + (size_t)ch * 4096;
        for (int k = 0; k < 16; k++) sin[tid + k * 256] = ip[tid + k * 256];
#pragma unroll
        for (int j = 0; j < 9; j++) w[j] = w_dw[ch * 9 + j];
        const float bv = b_dw[ch];
        __syncthreads();

        __half* op = ab16 + (size_t)b * (S_ * L_) + (size_t)s * 4096;
#pragma unroll
        for (int k = 0; k < 16; k++) {
            const int idx = k * 256 + tid;
            const int i = idx >> 6, j = idx & 63;
            float acc = bv;
#pragma unroll
            for (int di = 0; di < 3; di++) {
                const int ii = i + di - 1;
                if (ii < 0 || ii > 63) continue;
#pragma unroll
                for (int dj = 0; dj < 3; dj++) {
                    const int jj = j + dj - 1;
                    if (jj < 0 || jj > 63) continue;
                    acc += w[di * 3 + dj] * sin[(ii << 6) + jj];
                }
            }
            op[idx] = __float2half_rn(p[k] * acc);
        }
        __syncthreads();
    }

    {   // Cm channel -> cm (fp32)
        const int ch = 64 + s;
        const float* ip = braw + base + (size_t)ch * 4096;
        for (int k = 0; k < 16; k++) sin[tid + k * 256] = ip[tid + k * 256];
#pragma unroll
        for (int j = 0; j < 9; j++) w[j] = w_dw[ch * 9 + j];
        const float bv = b_dw[ch];
        __syncthreads();

        float* op = cm + (size_t)b * (S_ * L_) + (size_t)s * 4096;
#pragma unroll
        for (int k = 0; k < 16; k++) {
            const int idx = k * 256 + tid;
            const int i = idx >> 6, j = idx & 63;
            float acc = bv;
#pragma unroll
            for (int di = 0; di < 3; di++) {
                const int ii = i + di - 1;
                if (ii < 0 || ii > 63) continue;
#pragma unroll
                for (int dj = 0; dj < 3; dj++) {
                    const int jj = j + dj - 1;
                    if (jj < 0 || jj > 63) continue;
                    acc += w[di * 3 + dj] * sin[(ii << 6) + jj];
                }
            }
            op[idx] = acc;
        }
    }
}

// Gating: hg = h1 * (z*sigmoid(z) + Dskip), layout [o][b*64+s]
__global__ void __launch_bounds__(256) gate_kernel(
    const float* __restrict__ hz, float* __restrict__ hg,
    const float* __restrict__ Dskip)
{
    const int total = DM * B_ * S_;
    const int i = blockIdx.x * 256 + threadIdx.x;
    if (i >= total) return;
    const float h1 = hz[i];
    const float z  = hz[i + total];
    const float sig = 1.0f / (1.0f + expf(-z));
    hg[i] = h1 * (z * sig + Dskip[0]);
}

// ===========================================================================
// Host launch
// ===========================================================================
extern "C" void kernel_launch(void* const* d_in, const int* in_sizes, int n_in,
                              void* d_out, int out_size)
{
    (void)in_sizes; (void)n_in; (void)out_size;

    const float* x      = (const float*)d_in[0];   // [32,512,4096]
    const float* w_bcdt = (const float*)d_in[1];   // [192,512]
    const float* b_bcdt = (const float*)d_in[2];   // [192]
    const float* w_dw   = (const float*)d_in[3];   // [192,1,3,3]
    const float* b_dw   = (const float*)d_in[4];   // [192]
    const float* w_hz   = (const float*)d_in[5];   // [1024,512]
    const float* b_hz   = (const float*)d_in[6];   // [1024]
    const float* w_out  = (const float*)d_in[7];   // [512,512]
    const float* b_out  = (const float*)d_in[8];   // [512]
    const float* Dskip  = (const float*)d_in[10];  // [1] (A at [9] cancels in softmax)

    float* out = (float*)d_out;
    float* y   = out;                               // [32,512,4096]
    float* ho  = out + (size_t)B_ * DM * L_;        // [32,512,64]

    float *braw, *cm, *hpart, *hcb, *hz, *hg;
    __half *x16, *x16t, *ab16, *cm16t, *w16, *ho16;
    cudaGetSymbolAddress((void**)&braw,  g_braw);
    cudaGetSymbolAddress((void**)&cm,    g_cm);
    cudaGetSymbolAddress((void**)&hpart, g_hpart);
    cudaGetSymbolAddress((void**)&hcb,   g_hcb);
    cudaGetSymbolAddress((void**)&hz,    g_hz);
    cudaGetSymbolAddress((void**)&hg,    g_hg);
    cudaGetSymbolAddress((void**)&x16,   g_x16);
    cudaGetSymbolAddress((void**)&x16t,  g_x16t);
    cudaGetSymbolAddress((void**)&ab16,  g_ab16);
    cudaGetSymbolAddress((void**)&cm16t, g_cm16t);
    cudaGetSymbolAddress((void**)&w16,   g_w16);
    cudaGetSymbolAddress((void**)&ho16,  g_ho16);

    const dim3 blk(256);

    // 0a) x -> x16 (straight) + x16t (transposed)
    cvt_xt<<<dim3(L_ / 64, DM / 64, B_), blk>>>(x, x16, x16t, DM, L_);
    // 0b) w_bcdt -> fp16, zero-padded to 256 rows
    cvt_w<<<dim3((256 * DM + 255) / 256), blk>>>(w_bcdt, w16);

    // 1) braw[b] = w16 @ x16t[b]^T + b_bcdt   (M=192(256), N=4096, K=512)
    gemm_h16<128, 1><<<dim3(L_ / 128, 2, B_), blk>>>(
        w16, 0, DM,
        x16t, (long long)L_ * DM, DM,
        braw, (long long)3 * S_ * L_, L_, 0,
        b_bcdt, 192, DM);

    // 2) fused dwconv + softmax + ab16 / cm
    conv_softmax_ab<<<dim3(S_, B_), blk>>>(braw, w_dw, b_dw, cm, ab16);

    // 2b) cm -> cm16t (transposed fp16)
    cvt_xt<<<dim3(L_ / 64, 1, B_), blk>>>(cm, nullptr, cm16t, S_, L_);

    // 3) hpart[kseg] = x16[b] @ ab16[b]^T  (M=512, N=64, K=4096, split-K=4)
    gemm_h16<64, KSPLIT3><<<dim3(1, DM / 128, B_ * KSPLIT3), blk>>>(
        x16, (long long)DM * L_, L_,
        ab16, (long long)S_ * L_, L_,
        hpart, 64, B_ * S_, (long long)DM * B_ * S_,
        nullptr, DM, L_);

    // 4) reduce partials (and /AB_SCALE) -> hcb [512][2048]
    reduce_splitk<<<(DM * B_ * S_ / 4 + 255) / 256, blk>>>(
        (const float4*)hpart, (float4*)hcb);

    // 5) hz = w_hz @ hcb + b_hz   (M=1024, N=2048, K=512)
    gemm_mma<128, true, 1, 0><<<dim3(B_ * S_ / 128, 8, 1), blk>>>(
        w_hz, 0, DM,
        hcb, 0, B_ * S_,
        hz, 0, B_ * S_, 0,
        b_hz, 2 * DM, DM, nullptr);

    // 6) gating
    gate_kernel<<<(DM * B_ * S_ + 255) / 256, blk>>>(hz, hg, Dskip);

    // 7) ho = w_out @ hg + b_out -> d_out fp32 + ho16 fp16
    gemm_mma<128, true, 1, 1><<<dim3(B_ * S_ / 128, 4, 1), blk>>>(
        w_out, 0, DM,
        hg, 0, B_ * S_,
        ho, 0, 0, 0,
        b_out, DM, DM, ho16);

    // 8) y[b] = ho16[b] @ cm16t[b]^T   (M=512, N=4096, K=64)
    gemm_h16<128, 1><<<dim3(L_ / 128, 4, B_), blk>>>(
        ho16, (long long)DM * S_, S_,
        cm16t, (long long)L_ * S_, S_,
        y, (long long)DM * L_, L_, 0,
        nullptr, DM, S_);
}